// round 2
// baseline (speedup 1.0000x reference)
#include <cuda_runtime.h>
#include <cstdint>

// Router_63900523430579: MoE router on GB300
//   x [4,8192,2048] f32, W [64,2048] f32
//   scores = x @ W^T  (M=32768, N=64, K=2048)
//   out (f32): [0,65536)      top2 indices (as float)
//              [65536,131072) top2 softmax weights
//              [131072]       aux loss
//
// Strategy: fast fp32 FFMA2 GEMM + top-2 epilogue; tokens whose top-2/top-3
// margins are ambiguous (< 1e-4) get recomputed exactly in fp64 by a tiny
// fixup kernel, so index outputs match the reference bit-for-bit.

#define TM 128
#define TN 64
#define BK 16
#define RW 20            // padded row stride in floats (80B = 5*16B)
#define KDIM 2048
#define NCHUNK (KDIM / BK)
#define NTOK 32768
#define NCTA (NTOK / TM)

__device__ float g_part[NCTA * TN];   // per-CTA expert prob sums
__device__ int   g_cnt;               // ambiguous-token worklist
__device__ int   g_list[NTOK];

__device__ __forceinline__ unsigned cvta_s(const void* p) {
    return (unsigned)__cvta_generic_to_shared(p);
}
__device__ __forceinline__ void cp16(unsigned s, const void* g) {
    asm volatile("cp.async.cg.shared.global [%0], [%1], 16;\n" :: "r"(s), "l"(g));
}
#define CP_COMMIT() asm volatile("cp.async.commit_group;\n")
#define FFMA2(acc, a, b) \
    asm("fma.rn.f32x2 %0, %1, %2, %0;" : "+l"(acc) : "l"(a), "l"(b))

__global__ void __launch_bounds__(128)
router_kernel(const float* __restrict__ x, const float* __restrict__ W,
              float* __restrict__ out) {
    __shared__ __align__(16) unsigned char smem_raw[34304];
    float* xs = (float*)smem_raw;              // [2][TM*RW]
    float* ws = xs + 2 * TM * RW;              // [2][TN*RW]
    float* sc = (float*)smem_raw;              // epilogue overlay: [128][65]
    float* mm = sc + 128 * 65;                 // [128] per-token max
    float* iz = mm + 128;                      // [128] per-token 1/Z

    const int tid = threadIdx.x;
    const int tx = tid & 15;                   // token group (16)
    const int ty = tid >> 4;                   // expert group (8)

    const float* xg = x + (size_t)blockIdx.x * TM * KDIM;

    auto load_chunk = [&](int c, int buf) {
        const float* xc = xg + c * BK;
        float* xb = xs + buf * TM * RW;
        #pragma unroll
        for (int i = 0; i < 4; i++) {
            int idx = tid + i * 128;
            int r = idx >> 2, cc = idx & 3;
            cp16(cvta_s(xb + r * RW + cc * 4), xc + (size_t)r * KDIM + cc * 4);
        }
        const float* wc = W + c * BK;
        float* wb = ws + buf * TN * RW;
        #pragma unroll
        for (int i = 0; i < 2; i++) {
            int idx = tid + i * 128;
            int r = idx >> 2, cc = idx & 3;
            cp16(cvta_s(wb + r * RW + cc * 4), wc + (size_t)r * KDIM + cc * 4);
        }
        CP_COMMIT();
    };

    unsigned long long acc[8][8];
    #pragma unroll
    for (int j = 0; j < 8; j++)
        #pragma unroll
        for (int e = 0; e < 8; e++) acc[j][e] = 0ull;

    load_chunk(0, 0);
    load_chunk(1, 1);

    for (int c = 0; c < NCHUNK; c++) {
        if (c + 1 < NCHUNK) asm volatile("cp.async.wait_group 1;\n");
        else                asm volatile("cp.async.wait_group 0;\n");
        __syncthreads();

        const float* xb = xs + (c & 1) * TM * RW;
        const float* wb = ws + (c & 1) * TN * RW;

        #pragma unroll
        for (int kk = 0; kk < BK; kk += 4) {
            ulonglong2 xv[8];
            #pragma unroll
            for (int j = 0; j < 8; j++)
                xv[j] = *(const ulonglong2*)(xb + (tx + 16 * j) * RW + kk);
            #pragma unroll
            for (int eh = 0; eh < 8; eh += 4) {
                ulonglong2 wv[4];
                #pragma unroll
                for (int e = 0; e < 4; e++)
                    wv[e] = *(const ulonglong2*)(wb + (ty * 8 + eh + e) * RW + kk);
                #pragma unroll
                for (int j = 0; j < 8; j++)
                    #pragma unroll
                    for (int e = 0; e < 4; e++) {
                        FFMA2(acc[j][eh + e], xv[j].x, wv[e].x);
                        FFMA2(acc[j][eh + e], xv[j].y, wv[e].y);
                    }
            }
        }
        __syncthreads();
        if (c + 2 < NCHUNK) load_chunk(c + 2, c & 1);
    }

    // write scores to smem overlay
    #pragma unroll
    for (int j = 0; j < 8; j++) {
        int t = tx + 16 * j;
        #pragma unroll
        for (int e = 0; e < 8; e++) {
            unsigned long long a = acc[j][e];
            float lo = __uint_as_float((unsigned)a);
            float hi = __uint_as_float((unsigned)(a >> 32));
            sc[t * 65 + ty * 8 + e] = lo + hi;
        }
    }
    __syncthreads();

    // per-token epilogue: top-3 scan, softmax, ambiguity flag
    {
        const int t = tid;
        const float* row = sc + t * 65;
        float m = -3.0e38f; int i1 = 0;
        #pragma unroll 8
        for (int e = 0; e < 64; e++) {
            float v = row[e];
            if (v > m) { m = v; i1 = e; }
        }
        float m2 = -3.0e38f; int i2 = 0;
        #pragma unroll 8
        for (int e = 0; e < 64; e++) {
            if (e == i1) continue;
            float v = row[e];
            if (v > m2) { m2 = v; i2 = e; }
        }
        float m3 = -3.0e38f;
        #pragma unroll 8
        for (int e = 0; e < 64; e++) {
            if (e == i1 || e == i2) continue;
            float v = row[e];
            if (v > m3) m3 = v;
        }
        float Z = 0.0f;
        #pragma unroll 8
        for (int e = 0; e < 64; e++) Z += __expf(row[e] - m);
        mm[t] = m;
        iz[t] = 1.0f / Z;

        float e2 = __expf(m2 - m);
        float w1 = 1.0f / (1.0f + e2);

        size_t T = (size_t)blockIdx.x * TM + t;
        out[2 * T]     = (float)i1;
        out[2 * T + 1] = (float)i2;
        out[2 * (size_t)NTOK + 2 * T]     = w1;
        out[2 * (size_t)NTOK + 2 * T + 1] = e2 * w1;

        // flag tokens whose ordering could be numerically ambiguous
        if ((m - m2) < 1e-4f || (m2 - m3) < 1e-4f) {
            int w = atomicAdd(&g_cnt, 1);
            g_list[w] = (int)T;
        }
    }
    __syncthreads();

    // deterministic per-CTA expert-usage partials
    if (tid < TN) {
        float s = 0.0f;
        for (int t = 0; t < TM; t++)
            s += __expf(sc[t * 65 + tid] - mm[t]) * iz[t];
        g_part[(size_t)blockIdx.x * TN + tid] = s;
    }
}

__global__ void reset_kernel() { g_cnt = 0; }

// Exact fp64 recompute for ambiguous tokens (expected ~tens of tokens).
__global__ void __launch_bounds__(128)
fixup_kernel(const float* __restrict__ x, const float* __restrict__ W,
             float* __restrict__ out) {
    __shared__ double sh[64];
    const int n = g_cnt;
    const int e = threadIdx.x >> 1;
    const int h = threadIdx.x & 1;
    for (int w = blockIdx.x; w < n; w += gridDim.x) {
        const int tok = g_list[w];
        const float* xr = x + (size_t)tok * KDIM + h * 1024;
        const float* wr = W + (size_t)e * KDIM + h * 1024;
        double s = 0.0;
        for (int k = 0; k < 1024; k++)
            s += (double)xr[k] * (double)wr[k];
        s += __shfl_down_sync(0xffffffffu, s, 1);
        if (h == 0) sh[e] = s;
        __syncthreads();
        if (threadIdx.x == 0) {
            double m = -1e300; int i1 = 0;
            for (int q = 0; q < 64; q++)
                if (sh[q] > m) { m = sh[q]; i1 = q; }
            double m2 = -1e300; int i2 = 0;
            for (int q = 0; q < 64; q++) {
                if (q == i1) continue;
                if (sh[q] > m2) { m2 = sh[q]; i2 = q; }
            }
            double e2 = exp(m2 - m);
            double w1 = 1.0 / (1.0 + e2);
            out[2 * (size_t)tok]     = (float)i1;
            out[2 * (size_t)tok + 1] = (float)i2;
            out[2 * (size_t)NTOK + 2 * (size_t)tok]     = (float)w1;
            out[2 * (size_t)NTOK + 2 * (size_t)tok + 1] = (float)(e2 * w1);
        }
        __syncthreads();
    }
}

__global__ void aux_kernel(float* __restrict__ out) {
    int e = threadIdx.x;  // 32 threads; each handles experts e and e+32
    float u1 = 0.0f, u2 = 0.0f;
    for (int c = 0; c < NCTA; c++) {
        u1 += g_part[c * TN + e];
        u2 += g_part[c * TN + e + 32];
    }
    u1 *= (1.0f / (float)NTOK);
    u2 *= (1.0f / (float)NTOK);
    float v = u1 * u1 + u2 * u2;
    #pragma unroll
    for (int o = 16; o > 0; o >>= 1)
        v += __shfl_xor_sync(0xffffffffu, v, o);
    if (e == 0) out[131072] = 64.0f * v;
}

extern "C" void kernel_launch(void* const* d_in, const int* in_sizes, int n_in,
                              void* d_out, int out_size) {
    const float* x = (const float*)d_in[0];
    const float* W = (const float*)d_in[1];
    float* out = (float*)d_out;
    reset_kernel<<<1, 1>>>();
    router_kernel<<<NCTA, 128>>>(x, W, out);
    fixup_kernel<<<64, 128>>>(x, W, out);
    aux_kernel<<<1, 32>>>(out);
}

// round 3
// speedup vs baseline: 1.0071x; 1.0071x over previous
#include <cuda_runtime.h>
#include <cstdint>

// Router_63900523430579: MoE router on GB300
//   x [4,8192,2048] f32, W [64,2048] f32
//   scores = x @ W^T  (M=32768, N=64, K=2048)
//   out (f32): [0,65536)      top2 indices (as float)
//              [65536,131072) top2 softmax weights
//              [131072]       aux loss
//
// Strategy: fast fp32 FFMA2 GEMM + top-2 epilogue; tokens whose top-2/top-3
// margins are ambiguous (< 1e-4) get recomputed exactly in fp64 by a tiny
// fixup kernel, so index outputs match the reference bit-for-bit.

#define TM 128
#define TN 64
#define BK 16
#define RW 20            // padded row stride in floats (80B = 5*16B)
#define KDIM 2048
#define NCHUNK (KDIM / BK)
#define NTOK 32768
#define NCTA (NTOK / TM)

__device__ float g_part[NCTA * TN];   // per-CTA expert prob sums
__device__ int   g_cnt;               // ambiguous-token worklist
__device__ int   g_list[NTOK];

__device__ __forceinline__ unsigned cvta_s(const void* p) {
    return (unsigned)__cvta_generic_to_shared(p);
}
__device__ __forceinline__ void cp16(unsigned s, const void* g) {
    asm volatile("cp.async.cg.shared.global [%0], [%1], 16;\n" :: "r"(s), "l"(g));
}
#define CP_COMMIT() asm volatile("cp.async.commit_group;\n")
#define FFMA2(acc, a, b) \
    asm("fma.rn.f32x2 %0, %1, %2, %0;" : "+l"(acc) : "l"(a), "l"(b))

__global__ void __launch_bounds__(128)
router_kernel(const float* __restrict__ x, const float* __restrict__ W,
              float* __restrict__ out) {
    __shared__ __align__(16) unsigned char smem_raw[34304];
    float* xs = (float*)smem_raw;              // [2][TM*RW]
    float* ws = xs + 2 * TM * RW;              // [2][TN*RW]
    float* sc = (float*)smem_raw;              // epilogue overlay: [128][65]
    float* mm = sc + 128 * 65;                 // [128] per-token max
    float* iz = mm + 128;                      // [128] per-token 1/Z

    const int tid = threadIdx.x;
    const int tx = tid & 15;                   // token group (16)
    const int ty = tid >> 4;                   // expert group (8)

    const float* xg = x + (size_t)blockIdx.x * TM * KDIM;

    auto load_chunk = [&](int c, int buf) {
        const float* xc = xg + c * BK;
        float* xb = xs + buf * TM * RW;
        #pragma unroll
        for (int i = 0; i < 4; i++) {
            int idx = tid + i * 128;
            int r = idx >> 2, cc = idx & 3;
            cp16(cvta_s(xb + r * RW + cc * 4), xc + (size_t)r * KDIM + cc * 4);
        }
        const float* wc = W + c * BK;
        float* wb = ws + buf * TN * RW;
        #pragma unroll
        for (int i = 0; i < 2; i++) {
            int idx = tid + i * 128;
            int r = idx >> 2, cc = idx & 3;
            cp16(cvta_s(wb + r * RW + cc * 4), wc + (size_t)r * KDIM + cc * 4);
        }
        CP_COMMIT();
    };

    unsigned long long acc[8][8];
    #pragma unroll
    for (int j = 0; j < 8; j++)
        #pragma unroll
        for (int e = 0; e < 8; e++) acc[j][e] = 0ull;

    load_chunk(0, 0);
    load_chunk(1, 1);

    for (int c = 0; c < NCHUNK; c++) {
        if (c + 1 < NCHUNK) asm volatile("cp.async.wait_group 1;\n");
        else                asm volatile("cp.async.wait_group 0;\n");
        __syncthreads();

        const float* xb = xs + (c & 1) * TM * RW;
        const float* wb = ws + (c & 1) * TN * RW;

        #pragma unroll
        for (int kk = 0; kk < BK; kk += 4) {
            ulonglong2 xv[8];
            #pragma unroll
            for (int j = 0; j < 8; j++)
                xv[j] = *(const ulonglong2*)(xb + (tx + 16 * j) * RW + kk);
            #pragma unroll
            for (int eh = 0; eh < 8; eh += 4) {
                ulonglong2 wv[4];
                #pragma unroll
                for (int e = 0; e < 4; e++)
                    wv[e] = *(const ulonglong2*)(wb + (ty * 8 + eh + e) * RW + kk);
                #pragma unroll
                for (int j = 0; j < 8; j++)
                    #pragma unroll
                    for (int e = 0; e < 4; e++) {
                        FFMA2(acc[j][eh + e], xv[j].x, wv[e].x);
                        FFMA2(acc[j][eh + e], xv[j].y, wv[e].y);
                    }
            }
        }
        __syncthreads();
        if (c + 2 < NCHUNK) load_chunk(c + 2, c & 1);
    }

    // write scores to smem overlay
    #pragma unroll
    for (int j = 0; j < 8; j++) {
        int t = tx + 16 * j;
        #pragma unroll
        for (int e = 0; e < 8; e++) {
            unsigned long long a = acc[j][e];
            float lo = __uint_as_float((unsigned)a);
            float hi = __uint_as_float((unsigned)(a >> 32));
            sc[t * 65 + ty * 8 + e] = lo + hi;
        }
    }
    __syncthreads();

    // per-token epilogue: top-3 scan, softmax, ambiguity flag
    {
        const int t = tid;
        const float* row = sc + t * 65;
        float m = -3.0e38f; int i1 = 0;
        #pragma unroll 8
        for (int e = 0; e < 64; e++) {
            float v = row[e];
            if (v > m) { m = v; i1 = e; }
        }
        float m2 = -3.0e38f; int i2 = 0;
        #pragma unroll 8
        for (int e = 0; e < 64; e++) {
            if (e == i1) continue;
            float v = row[e];
            if (v > m2) { m2 = v; i2 = e; }
        }
        float m3 = -3.0e38f;
        #pragma unroll 8
        for (int e = 0; e < 64; e++) {
            if (e == i1 || e == i2) continue;
            float v = row[e];
            if (v > m3) m3 = v;
        }
        float Z = 0.0f;
        #pragma unroll 8
        for (int e = 0; e < 64; e++) Z += __expf(row[e] - m);
        mm[t] = m;
        iz[t] = 1.0f / Z;

        float e2 = __expf(m2 - m);
        float w1 = 1.0f / (1.0f + e2);

        size_t T = (size_t)blockIdx.x * TM + t;
        out[2 * T]     = (float)i1;
        out[2 * T + 1] = (float)i2;
        out[2 * (size_t)NTOK + 2 * T]     = w1;
        out[2 * (size_t)NTOK + 2 * T + 1] = e2 * w1;

        // flag tokens whose ordering could be numerically ambiguous
        if ((m - m2) < 1e-4f || (m2 - m3) < 1e-4f) {
            int w = atomicAdd(&g_cnt, 1);
            g_list[w] = (int)T;
        }
    }
    __syncthreads();

    // deterministic per-CTA expert-usage partials
    if (tid < TN) {
        float s = 0.0f;
        for (int t = 0; t < TM; t++)
            s += __expf(sc[t * 65 + tid] - mm[t]) * iz[t];
        g_part[(size_t)blockIdx.x * TN + tid] = s;
    }
}

__global__ void reset_kernel() { g_cnt = 0; }

// Exact fp64 recompute for ambiguous tokens (expected ~tens of tokens).
__global__ void __launch_bounds__(128)
fixup_kernel(const float* __restrict__ x, const float* __restrict__ W,
             float* __restrict__ out) {
    __shared__ double sh[64];
    const int n = g_cnt;
    const int e = threadIdx.x >> 1;
    const int h = threadIdx.x & 1;
    for (int w = blockIdx.x; w < n; w += gridDim.x) {
        const int tok = g_list[w];
        const float* xr = x + (size_t)tok * KDIM + h * 1024;
        const float* wr = W + (size_t)e * KDIM + h * 1024;
        double s = 0.0;
        for (int k = 0; k < 1024; k++)
            s += (double)xr[k] * (double)wr[k];
        s += __shfl_down_sync(0xffffffffu, s, 1);
        if (h == 0) sh[e] = s;
        __syncthreads();
        if (threadIdx.x == 0) {
            double m = -1e300; int i1 = 0;
            for (int q = 0; q < 64; q++)
                if (sh[q] > m) { m = sh[q]; i1 = q; }
            double m2 = -1e300; int i2 = 0;
            for (int q = 0; q < 64; q++) {
                if (q == i1) continue;
                if (sh[q] > m2) { m2 = sh[q]; i2 = q; }
            }
            double e2 = exp(m2 - m);
            double w1 = 1.0 / (1.0 + e2);
            out[2 * (size_t)tok]     = (float)i1;
            out[2 * (size_t)tok + 1] = (float)i2;
            out[2 * (size_t)NTOK + 2 * (size_t)tok]     = (float)w1;
            out[2 * (size_t)NTOK + 2 * (size_t)tok + 1] = (float)(e2 * w1);
        }
        __syncthreads();
    }
}

__global__ void aux_kernel(float* __restrict__ out) {
    int e = threadIdx.x;  // 32 threads; each handles experts e and e+32
    float u1 = 0.0f, u2 = 0.0f;
    for (int c = 0; c < NCTA; c++) {
        u1 += g_part[c * TN + e];
        u2 += g_part[c * TN + e + 32];
    }
    u1 *= (1.0f / (float)NTOK);
    u2 *= (1.0f / (float)NTOK);
    float v = u1 * u1 + u2 * u2;
    #pragma unroll
    for (int o = 16; o > 0; o >>= 1)
        v += __shfl_xor_sync(0xffffffffu, v, o);
    if (e == 0) out[131072] = 64.0f * v;
}

extern "C" void kernel_launch(void* const* d_in, const int* in_sizes, int n_in,
                              void* d_out, int out_size) {
    const float* x = (const float*)d_in[0];
    const float* W = (const float*)d_in[1];
    float* out = (float*)d_out;
    reset_kernel<<<1, 1>>>();
    router_kernel<<<NCTA, 128>>>(x, W, out);
    fixup_kernel<<<64, 128>>>(x, W, out);
    aux_kernel<<<1, 32>>>(out);
}